// round 6
// baseline (speedup 1.0000x reference)
#include <cuda_runtime.h>
#include <cuda_bf16.h>
#include <cuda_fp16.h>

#define NN 100000
#define EE 3200000
#define IND 128
#define HD 64
#define OD 2

// ---- scratch (__device__ globals per allocation rules) ----
__device__ int    g_cnt[NN];                 // in-degree (excl. self-loop)
__device__ float  g_dinv[NN];                // rsqrt(deg+1)
__device__ int    g_pexcl[NN];               // per-block exclusive scan partials
__device__ int    g_bsum[256];               // block sums
__device__ int    g_boff[256];               // block offsets
__device__ int    g_rowstart[NN + 1];        // CSR row offsets (by dst)
__device__ int    g_cursor[NN];              // fill cursors
__device__ int    g_csr[EE];                 // CSR payload: src node ids
__device__ __half g_h1s[(size_t)NN * HD];    // fp16: dinv[r] * (x @ W1)[r]   (12.8 MB)
__device__ __half g_a1[(size_t)NN * HD];     // fp16: relu(layer1 out)        (12.8 MB)
__device__ float  g_h2s[(size_t)NN * OD];    // fp32: dinv[r] * (a1 @ W2)[r]

// ---------------- histogram / normalization ----------------

__global__ void k_zero(int n) {
    int i = blockIdx.x * blockDim.x + threadIdx.x;
    if (i < n) g_cnt[i] = 0;
}

__global__ void k_hist(const int* __restrict__ ei, int e) {
    int stride = gridDim.x * blockDim.x;
    for (int i = blockIdx.x * blockDim.x + threadIdx.x; i < e; i += stride)
        atomicAdd(&g_cnt[ei[(size_t)e + i]], 1);
}

__global__ void k_dinv(int n) {
    int i = blockIdx.x * blockDim.x + threadIdx.x;
    if (i < n) g_dinv[i] = rsqrtf((float)g_cnt[i] + 1.0f);
}

// ---------------- 2-level exclusive scan (512 elems / block) ----------------

__global__ void __launch_bounds__(256) k_scan_local(int n) {
    __shared__ int wtot[8];
    int t = threadIdx.x, lane = t & 31, warp = t >> 5;
    int base = blockIdx.x * 512;
    int i0 = base + 2 * t;
    int a = (i0 < n) ? g_cnt[i0] : 0;
    int b = (i0 + 1 < n) ? g_cnt[i0 + 1] : 0;
    int tsum = a + b;
    int incl = tsum;
    #pragma unroll
    for (int o = 1; o < 32; o <<= 1) {
        int v = __shfl_up_sync(0xffffffffu, incl, o);
        if (lane >= o) incl += v;
    }
    if (lane == 31) wtot[warp] = incl;
    __syncthreads();
    if (t < 8) {
        int v = wtot[t], s = v;
        #pragma unroll
        for (int o = 1; o < 8; o <<= 1) {
            int u = __shfl_up_sync(0xffu, s, o);
            if (t >= o) s += u;
        }
        wtot[t] = s;
    }
    __syncthreads();
    int pref = (warp > 0 ? wtot[warp - 1] : 0);
    int excl = incl + pref - tsum;      // exclusive prefix at element 2t
    if (i0 < n)     g_pexcl[i0] = excl;
    if (i0 + 1 < n) g_pexcl[i0 + 1] = excl + a;
    if (t == 255) g_bsum[blockIdx.x] = wtot[7];
}

__global__ void __launch_bounds__(256) k_scan_block(int nblk) {
    __shared__ int wtot[8];
    int t = threadIdx.x, lane = t & 31, warp = t >> 5;
    int v = (t < nblk) ? g_bsum[t] : 0;
    int incl = v;
    #pragma unroll
    for (int o = 1; o < 32; o <<= 1) {
        int u = __shfl_up_sync(0xffffffffu, incl, o);
        if (lane >= o) incl += u;
    }
    if (lane == 31) wtot[warp] = incl;
    __syncthreads();
    if (t < 8) {
        int x = wtot[t], s = x;
        #pragma unroll
        for (int o = 1; o < 8; o <<= 1) {
            int u = __shfl_up_sync(0xffu, s, o);
            if (t >= o) s += u;
        }
        wtot[t] = s;
    }
    __syncthreads();
    int pref = (warp > 0 ? wtot[warp - 1] : 0);
    if (t < nblk) g_boff[t] = incl + pref - v;   // exclusive
}

__global__ void k_scan_add(int n, int e) {
    int i = blockIdx.x * blockDim.x + threadIdx.x;
    if (i < n) {
        int off = g_pexcl[i] + g_boff[i >> 9];
        g_rowstart[i] = off;
        g_cursor[i]   = off;
    }
    if (i == 0) g_rowstart[n] = e;
}

__global__ void k_fill(const int* __restrict__ ei, int e) {
    int stride = gridDim.x * blockDim.x;
    for (int i = blockIdx.x * blockDim.x + threadIdx.x; i < e; i += stride) {
        int src = ei[i];
        int dst = ei[(size_t)e + i];
        int p = atomicAdd(&g_cursor[dst], 1);
        g_csr[p] = src;
    }
}

// ---------------- gemm1: g_h1s[r] = fp16( dinv[r] * (x[r] @ W1) ) ----------------
// Persistent, 32-row tiles. Thread = 2 rows x 4 cols (8 acc). x staged k-major.

__global__ void __launch_bounds__(256) k_gemm1(const float* __restrict__ x,
                                               const float* __restrict__ W1, int n) {
    __shared__ float Ws[IND * HD];     // 32 KB
    __shared__ float xsT[IND * 32];    // 16 KB, k-major: xsT[k*32 + r]
    int t = threadIdx.x;
    for (int i = t; i < IND * HD; i += 256) Ws[i] = W1[i];

    int r0 = (t >> 4) * 2;             // 0,2,..,30
    int r1 = r0 + 1;
    int c4 = (t & 15) * 4;             // 0..60
    int ntiles = (n + 31) / 32;

    for (int tile = blockIdx.x; tile < ntiles; tile += gridDim.x) {
        int rowBase = tile * 32;
        __syncthreads();
        for (int i = t; i < 1024; i += 256) {
            int row = i & 31;
            int cc  = (i >> 5) * 4;
            float4 v = make_float4(0.f, 0.f, 0.f, 0.f);
            if (rowBase + row < n)
                v = *(const float4*)&x[(size_t)(rowBase + row) * IND + cc];
            xsT[(cc + 0) * 32 + row] = v.x;
            xsT[(cc + 1) * 32 + row] = v.y;
            xsT[(cc + 2) * 32 + row] = v.z;
            xsT[(cc + 3) * 32 + row] = v.w;
        }
        __syncthreads();

        float a00 = 0.f, a01 = 0.f, a02 = 0.f, a03 = 0.f;
        float a10 = 0.f, a11 = 0.f, a12 = 0.f, a13 = 0.f;
        #pragma unroll 16
        for (int k = 0; k < IND; k++) {
            float4 w = *(const float4*)&Ws[k * HD + c4];
            float x0 = xsT[k * 32 + r0];
            float x1 = xsT[k * 32 + r1];
            a00 += x0 * w.x; a01 += x0 * w.y; a02 += x0 * w.z; a03 += x0 * w.w;
            a10 += x1 * w.x; a11 += x1 * w.y; a12 += x1 * w.z; a13 += x1 * w.w;
        }
        int row0 = rowBase + r0, row1 = rowBase + r1;
        if (row0 < n) {
            float d = g_dinv[row0];
            size_t o = (size_t)row0 * HD + c4;
            *(__half2*)&g_h1s[o]     = __floats2half2_rn(a00 * d, a01 * d);
            *(__half2*)&g_h1s[o + 2] = __floats2half2_rn(a02 * d, a03 * d);
        }
        if (row1 < n) {
            float d = g_dinv[row1];
            size_t o = (size_t)row1 * HD + c4;
            *(__half2*)&g_h1s[o]     = __floats2half2_rn(a10 * d, a11 * d);
            *(__half2*)&g_h1s[o + 2] = __floats2half2_rn(a12 * d, a13 * d);
        }
    }
}

// ---------------- gather1: a1[dst] = relu(dinv[dst]*(sum h1s[src] + h1s[dst]) + b1) ----------------
// Warp per dst row; lane covers 2 cols via one half2 (4B) -> 128B (1 line) per edge row.

__global__ void __launch_bounds__(256) k_gather1(const float* __restrict__ b1, int n) {
    int lane = threadIdx.x & 31;
    int row = blockIdx.x * 8 + (threadIdx.x >> 5);
    if (row >= n) return;
    int start = g_rowstart[row];
    int end   = g_rowstart[row + 1];
    int c = lane * 2;

    float2 acc = __half22float2(*(const __half2*)&g_h1s[(size_t)row * HD + c]); // self
    int j = start;
    while (j + 32 <= end) {
        int idx = g_csr[j + lane];
        #pragma unroll 8
        for (int k = 0; k < 32; k++) {
            int s = __shfl_sync(0xffffffffu, idx, k);
            float2 v = __half22float2(*(const __half2*)&g_h1s[(size_t)s * HD + c]);
            acc.x += v.x; acc.y += v.y;
        }
        j += 32;
    }
    if (j < end) {
        int m = end - j;
        int idx = (lane < m) ? g_csr[j + lane] : 0;
        for (int k = 0; k < m; k++) {
            int s = __shfl_sync(0xffffffffu, idx, k);
            float2 v = __half22float2(*(const __half2*)&g_h1s[(size_t)s * HD + c]);
            acc.x += v.x; acc.y += v.y;
        }
    }
    float d = g_dinv[row];
    float r0 = fmaxf(acc.x * d + b1[c], 0.f);
    float r1 = fmaxf(acc.y * d + b1[c + 1], 0.f);
    *(__half2*)&g_a1[(size_t)row * HD + c] = __floats2half2_rn(r0, r1);
}

// ---------------- gemm2: g_h2s[r] = dinv[r] * (a1[r] @ W2) ----------------

__global__ void __launch_bounds__(256) k_gemm2(const float* __restrict__ W2, int n) {
    __shared__ float Ws[HD * OD];
    for (int i = threadIdx.x; i < HD * OD; i += blockDim.x) Ws[i] = W2[i];
    __syncthreads();
    int i = blockIdx.x * blockDim.x + threadIdx.x;
    if (i >= n) return;
    float a0 = 0.f, a1 = 0.f;
    const __half2* h = (const __half2*)&g_a1[(size_t)i * HD];
    #pragma unroll
    for (int k = 0; k < HD / 2; k++) {
        float2 v = __half22float2(h[k]);
        a0 += v.x * Ws[(2 * k) * 2]     + v.y * Ws[(2 * k + 1) * 2];
        a1 += v.x * Ws[(2 * k) * 2 + 1] + v.y * Ws[(2 * k + 1) * 2 + 1];
    }
    float d = g_dinv[i];
    *(float2*)&g_h2s[(size_t)i * OD] = make_float2(a0 * d, a1 * d);
}

// ---------------- gather2: out[dst] = dinv[dst]*(sum h2s[src] + h2s[dst]) + b2 ----------------

__global__ void __launch_bounds__(256) k_gather2(const float* __restrict__ b2,
                                                 float* __restrict__ out, int n) {
    int lane = threadIdx.x & 31;
    int row = blockIdx.x * 8 + (threadIdx.x >> 5);
    if (row >= n) return;
    int start = g_rowstart[row];
    int end   = g_rowstart[row + 1];

    float2 acc = make_float2(0.f, 0.f);
    for (int j = start + lane; j < end; j += 32) {
        int s = g_csr[j];
        float2 v = *(const float2*)&g_h2s[(size_t)s * OD];
        acc.x += v.x; acc.y += v.y;
    }
    #pragma unroll
    for (int o = 16; o > 0; o >>= 1) {
        acc.x += __shfl_xor_sync(0xffffffffu, acc.x, o);
        acc.y += __shfl_xor_sync(0xffffffffu, acc.y, o);
    }
    if (lane == 0) {
        float2 self = *(const float2*)&g_h2s[(size_t)row * OD];
        float d = g_dinv[row];
        *(float2*)&out[(size_t)row * OD] =
            make_float2((acc.x + self.x) * d + b2[0],
                        (acc.y + self.y) * d + b2[1]);
    }
}

// ---------------- launch ----------------

extern "C" void kernel_launch(void* const* d_in, const int* in_sizes, int n_in,
                              void* d_out, int out_size) {
    const float* x  = (const float*)d_in[0];
    const int*   ei = (const int*)d_in[1];       // int32 (JAX x64 disabled)
    const float* W1 = (const float*)d_in[2];
    const float* b1 = (const float*)d_in[3];
    const float* W2 = (const float*)d_in[4];
    const float* b2 = (const float*)d_in[5];
    float* out = (float*)d_out;

    int n = in_sizes[0] / IND;    // 100000
    int e = in_sizes[1] / 2;      // 3200000
    int nblk = (n + 511) / 512;   // 196

    int nb256 = (n + 255) / 256;
    k_zero      <<<nb256, 256>>>(n);
    k_hist      <<<2048, 256>>>(ei, e);
    k_dinv      <<<nb256, 256>>>(n);
    k_scan_local<<<nblk, 256>>>(n);
    k_scan_block<<<1, 256>>>(nblk);
    k_scan_add  <<<nb256, 256>>>(n, e);
    k_fill      <<<2048, 256>>>(ei, e);
    k_gemm1     <<<592, 256>>>(x, W1, n);
    k_gather1   <<<(n + 7) / 8, 256>>>(b1, n);
    k_gemm2     <<<nb256, 256>>>(W2, n);
    k_gather2   <<<(n + 7) / 8, 256>>>(b2, out, n);
}